// round 14
// baseline (speedup 1.0000x reference)
#include <cuda_runtime.h>
#include <cuda_bf16.h>
#include <cstdint>

// Problem constants (fixed shapes)
constexpr int B_  = 2;
constexpr int S_  = 2048;
constexpr int D_  = 1024;
constexpr int H_  = 16;
constexpr int M_  = B_ * S_;            // 4096
constexpr size_t SS_ = (size_t)S_ * S_; // 4M
constexpr size_t MD_ = (size_t)M_ * D_;
constexpr size_t DD_ = (size_t)D_ * D_;

// ---------------------------------------------------------------------------
// Device-global scratch (pooled for batched GEMM addressing)
// ---------------------------------------------------------------------------
__device__ float g_att[(size_t)B_ * H_ * SS_];            // 512 MB fp32 scores

__device__ __nv_bfloat16 g_att_hi[(size_t)B_ * H_ * SS_]; // 256 MB
__device__ __nv_bfloat16 g_att_lo[(size_t)B_ * H_ * SS_];

__device__ __nv_bfloat16 g_in_hi [3 * MD_], g_in_lo [3 * MD_];  // qi,ki,vi
__device__ __nv_bfloat16 g_w_hi  [4 * DD_], g_w_lo  [4 * DD_];  // Wq,Wk,Wv,Wo
__device__ __nv_bfloat16 g_qkv_hi[3 * MD_], g_qkv_lo[3 * MD_];  // q,k,v
__device__ __nv_bfloat16 g_x_hi  [MD_],     g_x_lo  [MD_];
__device__ __nv_bfloat16 g_vt_hi[(size_t)B_ * H_ * 64 * S_];    // [bh][64][2048]
__device__ __nv_bfloat16 g_vt_lo[(size_t)B_ * H_ * 64 * S_];

// ---------------------------------------------------------------------------
// PTX helpers (compute_103-baseline safe: mma.sync / ldmatrix / cp.async)
// ---------------------------------------------------------------------------
__device__ __forceinline__ uint32_t smem_u32(const void* p) {
    uint32_t a;
    asm("{ .reg .u64 t; cvta.to.shared.u64 t, %1; cvt.u32.u64 %0, t; }"
        : "=r"(a) : "l"(p));
    return a;
}
__device__ __forceinline__ void cp16(uint32_t dst, const void* src) {
    asm volatile("cp.async.cg.shared.global [%0], [%1], 16;"
                 :: "r"(dst), "l"(src));
}
#define CP_COMMIT() asm volatile("cp.async.commit_group;" ::: "memory")
#define CP_WAIT(n)  asm volatile("cp.async.wait_group %0;" :: "n"(n) : "memory")

#define LDSM_X4(r, addr)                                                       \
    asm volatile("ldmatrix.sync.aligned.m8n8.x4.shared.b16 {%0,%1,%2,%3},[%4];"\
                 : "=r"((r)[0]), "=r"((r)[1]), "=r"((r)[2]), "=r"((r)[3])      \
                 : "r"(addr))
#define LDSM_X2(r, addr)                                                       \
    asm volatile("ldmatrix.sync.aligned.m8n8.x2.shared.b16 {%0,%1},[%2];"      \
                 : "=r"((r)[0]), "=r"((r)[1]) : "r"(addr))
#define MMA16816(c, a, b)                                                      \
    asm volatile("mma.sync.aligned.m16n8k16.row.col.f32.bf16.bf16.f32 "        \
                 "{%0,%1,%2,%3},{%4,%5,%6,%7},{%8,%9},{%0,%1,%2,%3};"          \
                 : "+f"((c)[0]), "+f"((c)[1]), "+f"((c)[2]), "+f"((c)[3])      \
                 : "r"((a)[0]), "r"((a)[1]), "r"((a)[2]), "r"((a)[3]),         \
                   "r"((b)[0]), "r"((b)[1]))

__device__ __forceinline__ void stcs_f2(float* p, float2 v) {
    asm volatile("st.global.cs.v2.f32 [%0], {%1, %2};"
                 :: "l"(p), "f"(v.x), "f"(v.y) : "memory");
}

__device__ __forceinline__ __nv_bfloat162 split_pair(float a, float b,
                                                     __nv_bfloat162& lo) {
    __nv_bfloat16 ha = __float2bfloat16(a);
    __nv_bfloat16 hb = __float2bfloat16(b);
    lo = __nv_bfloat162(__float2bfloat16(a - __bfloat162float(ha)),
                        __float2bfloat16(b - __bfloat162float(hb)));
    return __nv_bfloat162(ha, hb);
}

__device__ __forceinline__ void split_store4(const float4* x,
                                             __nv_bfloat162* hi,
                                             __nv_bfloat162* lo, int i) {
    float4 v = x[i];
    __nv_bfloat162 l0, l1;
    __nv_bfloat162 h0 = split_pair(v.x, v.y, l0);
    __nv_bfloat162 h1 = split_pair(v.z, v.w, l1);
    hi[2 * i] = h0; hi[2 * i + 1] = h1;
    lo[2 * i] = l0; lo[2 * i + 1] = l1;
}

// ---------------------------------------------------------------------------
// Fused splits into pooled buffers
// ---------------------------------------------------------------------------
__global__ __launch_bounds__(256) void split3_kernel(
    const float4* __restrict__ s0, const float4* __restrict__ s1,
    const float4* __restrict__ s2,
    __nv_bfloat162* __restrict__ hi, __nv_bfloat162* __restrict__ lo, int n4)
{
    int i = blockIdx.x * 256 + threadIdx.x;
    const float4* s = blockIdx.y == 0 ? s0 : blockIdx.y == 1 ? s1 : s2;
    split_store4(s, hi + (size_t)blockIdx.y * n4 * 2,
                 lo + (size_t)blockIdx.y * n4 * 2, i);
}

__global__ __launch_bounds__(256) void split4_kernel(
    const float4* __restrict__ s0, const float4* __restrict__ s1,
    const float4* __restrict__ s2, const float4* __restrict__ s3,
    __nv_bfloat162* __restrict__ hi, __nv_bfloat162* __restrict__ lo, int n4)
{
    int i = blockIdx.x * 256 + threadIdx.x;
    const float4* s = blockIdx.y == 0 ? s0 : blockIdx.y == 1 ? s1
                    : blockIdx.y == 2 ? s2 : s3;
    split_store4(s, hi + (size_t)blockIdx.y * n4 * 2,
                 lo + (size_t)blockIdx.y * n4 * 2, i);
}

// ---------------------------------------------------------------------------
// V hi/lo [b, k(2048), d(1024)] bf16 -> Vt hi/lo [bh, d(64), k(2048)] bf16
// ---------------------------------------------------------------------------
__global__ __launch_bounds__(256) void transpose_v_bf16(
    const __nv_bfloat16* __restrict__ Vh, const __nv_bfloat16* __restrict__ Vl,
    __nv_bfloat16* __restrict__ hi, __nv_bfloat16* __restrict__ lo)
{
    __shared__ __nv_bfloat16 th[32][34], tl[32][34];
    const int b  = blockIdx.z;
    const int k0 = blockIdx.y * 32;
    const int d0 = blockIdx.x * 32;
    const int tx = threadIdx.x & 31, ty = threadIdx.x >> 5;
#pragma unroll
    for (int i = 0; i < 4; i++) {
        int k = k0 + ty + i * 8;
        size_t src = ((size_t)b * S_ + k) * D_ + d0 + tx;
        th[ty + i * 8][tx] = Vh[src];
        tl[ty + i * 8][tx] = Vl[src];
    }
    __syncthreads();
#pragma unroll
    for (int i = 0; i < 4; i++) {
        int d = d0 + ty + i * 8;
        int h = d >> 6, dh = d & 63;
        size_t o = ((size_t)(b * H_ + h) * 64 + dh) * S_ + k0 + tx;
        hi[o] = th[tx][ty + i * 8];
        lo[o] = tl[tx][ty + i * 8];
    }
}

// ---------------------------------------------------------------------------
// Generic NT bf16x3 GEMM, 256 threads, 2-stage cp.async, templated macro-tile.
// MINCTA forces register cap for multi-CTA occupancy (store-bound variants).
// ---------------------------------------------------------------------------
template<int BM, int BN, int WGM, int WGN, int OUT16, int MINCTA = 1>
__global__ __launch_bounds__(256, MINCTA) void gemm_bf16x3_mma(
    const __nv_bfloat16* __restrict__ Ahi, const __nv_bfloat16* __restrict__ Alo,
    const __nv_bfloat16* __restrict__ Bhi, const __nv_bfloat16* __restrict__ Blo,
    float* __restrict__ C, __nv_bfloat16* __restrict__ Chi,
    __nv_bfloat16* __restrict__ Clo, int K, int lda, int ldb, int ldc,
    size_t zsA1, size_t zsA2, size_t zsB1, size_t zsB2,
    size_t zsC1, size_t zsC2, float scale)
{
    constexpr int NTHR = 256;
    constexpr int BK = 32;
    constexpr int WTM = BM / WGM;
    constexpr int WTN = BN / WGN;
    constexpr int MT  = WTM / 16;
    constexpr int NT  = WTN / 8;
    constexpr int LDSR = BK + 8;
    constexpr int A_BYTES = BM * LDSR * 2;
    constexpr int B_BYTES = BN * LDSR * 2;
    constexpr int STAGE   = 2 * A_BYTES + 2 * B_BYTES;
    constexpr int CHUNKS  = (2 * BM + 2 * BN) * 4;
    static_assert(CHUNKS % NTHR == 0, "loader balance");

    extern __shared__ char smem_raw[];
    const uint32_t sbase = smem_u32(smem_raw);

    const int tid  = threadIdx.x;
    const int wid  = tid >> 5, lane = tid & 31;
    const int wm   = wid / WGN, wn = wid % WGN;
    const int bm   = blockIdx.y * BM;
    const int bn   = blockIdx.x * BN;
    const int z    = blockIdx.z;

    const size_t offA = (size_t)(z & 15) * zsA1 + (size_t)(z >> 4) * zsA2;
    const size_t offB = (size_t)(z & 15) * zsB1 + (size_t)(z >> 4) * zsB2;
    const size_t offC = (size_t)(z & 15) * zsC1 + (size_t)(z >> 4) * zsC2;
    const __nv_bfloat16* pAh = Ahi + offA;
    const __nv_bfloat16* pAl = Alo + offA;
    const __nv_bfloat16* pBh = Bhi + offB;
    const __nv_bfloat16* pBl = Blo + offB;

    float acc[MT][NT][4];
#pragma unroll
    for (int i = 0; i < MT; i++)
#pragma unroll
        for (int j = 0; j < NT; j++)
#pragma unroll
            for (int q = 0; q < 4; q++) acc[i][j][q] = 0.0f;

    const int NC = K / BK;

    auto issue = [&](int c) {
        const uint32_t sb = sbase + (uint32_t)(c & 1) * STAGE;
        const int k0 = c * BK;
#pragma unroll
        for (int it = 0; it < CHUNKS / NTHR; it++) {
            int idx = tid + it * NTHR;
            int r4 = idx >> 2, kc = idx & 3;
            const __nv_bfloat16* src;
            uint32_t dst;
            if (r4 < BM) {
                src = pAh + (size_t)(bm + r4) * lda + k0 + kc * 8;
                dst = sb + (uint32_t)(r4 * (LDSR * 2) + kc * 16);
            } else if (r4 < 2 * BM) {
                int r = r4 - BM;
                src = pAl + (size_t)(bm + r) * lda + k0 + kc * 8;
                dst = sb + A_BYTES + (uint32_t)(r * (LDSR * 2) + kc * 16);
            } else if (r4 < 2 * BM + BN) {
                int r = r4 - 2 * BM;
                src = pBh + (size_t)(bn + r) * ldb + k0 + kc * 8;
                dst = sb + 2 * A_BYTES + (uint32_t)(r * (LDSR * 2) + kc * 16);
            } else {
                int r = r4 - 2 * BM - BN;
                src = pBl + (size_t)(bn + r) * ldb + k0 + kc * 8;
                dst = sb + 2 * A_BYTES + B_BYTES + (uint32_t)(r * (LDSR * 2) + kc * 16);
            }
            cp16(dst, src);
        }
        CP_COMMIT();
    };

    issue(0);

    for (int c = 0; c < NC; c++) {
        if (c + 1 < NC) { issue(c + 1); CP_WAIT(1); }
        else            { CP_WAIT(0); }
        __syncthreads();

        const uint32_t sA  = sbase + (uint32_t)(c & 1) * STAGE;
        const uint32_t sB  = sA + 2 * A_BYTES;

        const int arow = lane & 15;
        const int acb  = (lane >> 4) * 8;
        const int brow = lane & 7;
        const int bcb  = ((lane >> 3) & 1) * 8;

#pragma unroll
        for (int ks = 0; ks < 2; ks++) {
            uint32_t ahi[MT][4], alo[MT][4], bhi[NT][2], blo[NT][2];
#pragma unroll
            for (int mt = 0; mt < MT; mt++) {
                uint32_t off = (uint32_t)(((wm * WTM + mt * 16 + arow) * LDSR
                                           + ks * 16 + acb) * 2);
                LDSM_X4(ahi[mt], sA + off);
                LDSM_X4(alo[mt], sA + A_BYTES + off);
            }
#pragma unroll
            for (int nt = 0; nt < NT; nt++) {
                uint32_t off = (uint32_t)(((wn * WTN + nt * 8 + brow) * LDSR
                                           + ks * 16 + bcb) * 2);
                LDSM_X2(bhi[nt], sB + off);
                LDSM_X2(blo[nt], sB + B_BYTES + off);
            }
#pragma unroll
            for (int mt = 0; mt < MT; mt++)
#pragma unroll
                for (int nt = 0; nt < NT; nt++) {
                    MMA16816(acc[mt][nt], ahi[mt], bhi[nt]);
                    MMA16816(acc[mt][nt], ahi[mt], blo[nt]);
                    MMA16816(acc[mt][nt], alo[mt], bhi[nt]);
                }
        }
        __syncthreads();
    }

    const int erow = lane >> 2;
    const int ecol = 2 * (lane & 3);
#pragma unroll
    for (int mt = 0; mt < MT; mt++) {
        const int row = bm + wm * WTM + mt * 16 + erow;
#pragma unroll
        for (int nt = 0; nt < NT; nt++) {
            const int col = bn + wn * WTN + nt * 8 + ecol;
            if constexpr (OUT16) {
                __nv_bfloat162 l0, l1;
                __nv_bfloat162 h0 = split_pair(acc[mt][nt][0] * scale,
                                               acc[mt][nt][1] * scale, l0);
                __nv_bfloat162 h1 = split_pair(acc[mt][nt][2] * scale,
                                               acc[mt][nt][3] * scale, l1);
                size_t o0 = offC + (size_t)row * ldc + col;
                size_t o1 = offC + (size_t)(row + 8) * ldc + col;
                *(__nv_bfloat162*)(Chi + o0) = h0;
                *(__nv_bfloat162*)(Clo + o0) = l0;
                *(__nv_bfloat162*)(Chi + o1) = h1;
                *(__nv_bfloat162*)(Clo + o1) = l1;
            } else {
                float* pC = C + offC;
                stcs_f2(pC + (size_t)row * ldc + col,
                        make_float2(acc[mt][nt][0] * scale, acc[mt][nt][1] * scale));
                stcs_f2(pC + (size_t)(row + 8) * ldc + col,
                        make_float2(acc[mt][nt][2] * scale, acc[mt][nt][3] * scale));
            }
        }
    }
}

// ---------------------------------------------------------------------------
// softmax over the HEAD axis, vectorized over k (float2 per thread).
// ---------------------------------------------------------------------------
__global__ __launch_bounds__(256) void softmax_h_split_v2(
    const float* __restrict__ att, __nv_bfloat16* __restrict__ hi,
    __nv_bfloat16* __restrict__ lo)
{
    const size_t SS2 = SS_ / 2;
    size_t idx = (size_t)blockIdx.x * 256 + threadIdx.x;
    size_t b   = idx >> 21;
    size_t rem = idx & (SS2 - 1);
    size_t base = b * (size_t)H_ * SS_ + rem * 2;

    float2 v[H_];
    float mx = -1e30f, my = -1e30f;
#pragma unroll
    for (int h = 0; h < H_; h++) {
        v[h] = *(const float2*)(att + base + (size_t)h * SS_);
        mx = fmaxf(mx, v[h].x);
        my = fmaxf(my, v[h].y);
    }
    float sx = 0.0f, sy = 0.0f;
#pragma unroll
    for (int h = 0; h < H_; h++) {
        v[h].x = __expf(v[h].x - mx);
        v[h].y = __expf(v[h].y - my);
        sx += v[h].x;
        sy += v[h].y;
    }
    float ix = 1.0f / sx, iy = 1.0f / sy;
#pragma unroll
    for (int h = 0; h < H_; h++) {
        float px = v[h].x * ix, py = v[h].y * iy;
        __nv_bfloat162 l;
        __nv_bfloat162 hv = split_pair(px, py, l);
        size_t o = base + (size_t)h * SS_;
        *(__nv_bfloat162*)(hi + o) = hv;
        *(__nv_bfloat162*)(lo + o) = l;
    }
}

// ---------------------------------------------------------------------------
extern "C" void kernel_launch(void* const* d_in, const int* in_sizes, int n_in,
                              void* d_out, int out_size)
{
    (void)in_sizes; (void)n_in; (void)out_size;
    const float* qi = (const float*)d_in[0];
    const float* ki = (const float*)d_in[1];
    const float* vi = (const float*)d_in[2];
    // d_in[3] = mask: reference discards masked_fill -> unused
    const float* Wq = (const float*)d_in[4];
    const float* Wk = (const float*)d_in[5];
    const float* Wv = (const float*)d_in[6];
    const float* Wo = (const float*)d_in[7];
    float* out = (float*)d_out;

    float* gatt;
    cudaGetSymbolAddress((void**)&gatt, g_att);

    __nv_bfloat16 *inh, *inl, *wh, *wl, *qkvh, *qkvl, *xh, *xl, *vth, *vtl, *ath, *atl;
    cudaGetSymbolAddress((void**)&inh,  g_in_hi);  cudaGetSymbolAddress((void**)&inl,  g_in_lo);
    cudaGetSymbolAddress((void**)&wh,   g_w_hi);   cudaGetSymbolAddress((void**)&wl,   g_w_lo);
    cudaGetSymbolAddress((void**)&qkvh, g_qkv_hi); cudaGetSymbolAddress((void**)&qkvl, g_qkv_lo);
    cudaGetSymbolAddress((void**)&xh,   g_x_hi);   cudaGetSymbolAddress((void**)&xl,   g_x_lo);
    cudaGetSymbolAddress((void**)&vth,  g_vt_hi);  cudaGetSymbolAddress((void**)&vtl,  g_vt_lo);
    cudaGetSymbolAddress((void**)&ath,  g_att_hi); cudaGetSymbolAddress((void**)&atl,  g_att_lo);

    // 256x128 big tile for projections / out-proj; 128x64 for attn@V;
    // scores: 128x64-output, 2 CTAs/SM (store-MLP-bound, K=64).
    auto* gemm_f32 = gemm_bf16x3_mma<256, 128, 4, 2, 0, 1>;
    auto* gemm_b16 = gemm_bf16x3_mma<256, 128, 4, 2, 1, 1>;
    auto* gemm_nar = gemm_bf16x3_mma<128, 64, 4, 2, 1, 1>;
    auto* gemm_sco = gemm_bf16x3_mma<128, 64, 2, 4, 0, 2>;
    constexpr int SMEM_BIG = 2 * (2 * 256 * 40 * 2 + 2 * 128 * 40 * 2); // 122880
    constexpr int SMEM_NAR = 2 * (2 * 128 * 40 * 2 + 2 * 64 * 40 * 2);  // 61440
    cudaFuncSetAttribute(gemm_f32, cudaFuncAttributeMaxDynamicSharedMemorySize, SMEM_BIG);
    cudaFuncSetAttribute(gemm_b16, cudaFuncAttributeMaxDynamicSharedMemorySize, SMEM_BIG);
    cudaFuncSetAttribute(gemm_nar, cudaFuncAttributeMaxDynamicSharedMemorySize, SMEM_NAR);
    cudaFuncSetAttribute(gemm_sco, cudaFuncAttributeMaxDynamicSharedMemorySize, SMEM_NAR);

    const int nInp4 = (int)(MD_ / 4);   // 1,048,576
    const int nW4   = (int)(DD_ / 4);   // 262,144

    // launch 0: split inputs (qi, ki, vi) -> pooled g_in
    dim3 gs3(nInp4 / 256, 3);
    split3_kernel<<<gs3, 256>>>((const float4*)qi, (const float4*)ki, (const float4*)vi,
                                (__nv_bfloat162*)inh, (__nv_bfloat162*)inl, nInp4);

    // launch 1: split weights -> pooled g_w
    dim3 gs4(nW4 / 256, 4);
    split4_kernel<<<gs4, 256>>>((const float4*)Wq, (const float4*)Wk,
                                (const float4*)Wv, (const float4*)Wo,
                                (__nv_bfloat162*)wh, (__nv_bfloat162*)wl, nW4);

    // launch 2: batched Q/K/V projections (z selects), emit bf16 hi/lo
    dim3 gproj(D_ / 128, M_ / 256, 3);   // (8, 16, 3) = 384 CTAs
    gemm_b16<<<gproj, 256, SMEM_BIG>>>(inh, inl, wh, wl, nullptr, qkvh, qkvl,
                                       D_, D_, D_, D_,
                                       MD_, 0, DD_, 0, MD_, 0, 1.0f);

    // launch 3 (ncu capture slot): scores[bh] = (Q_h @ K_h^T) / 8  (fp32, .cs)
    dim3 gsc(S_ / 64, S_ / 128, B_ * H_);   // (32, 16, 32) = 16384 CTAs
    gemm_sco<<<gsc, 256, SMEM_NAR>>>(qkvh, qkvl, qkvh + MD_, qkvl + MD_,
                                     gatt, nullptr, nullptr,
                                     64, D_, D_, S_,
                                     64, (size_t)S_ * D_,
                                     64, (size_t)S_ * D_,
                                     SS_, (size_t)H_ * SS_, 0.125f);

    // launch 4: transpose v hi/lo -> [bh][64][2048]
    dim3 gtr(D_ / 32, S_ / 32, B_);
    transpose_v_bf16<<<gtr, 256>>>(qkvh + 2 * MD_, qkvl + 2 * MD_, vth, vtl);

    // launch 5: softmax over heads (float2-vectorized) -> attn hi/lo bf16
    int smx_blocks = (int)(((size_t)B_ * SS_ / 2) / 256);   // 16384
    softmax_h_split_v2<<<smx_blocks, 256>>>(gatt, ath, atl);

    // launch 6: x[bh] = attn[bh] @ Vt[bh]^T  (N=64), emits bf16 hi/lo
    dim3 gav(1, S_ / 128, B_ * H_);      // (1, 16, 32) = 512 CTAs
    gemm_nar<<<gav, 256, SMEM_NAR>>>(ath, atl, vth, vtl, nullptr, xh, xl,
                                     S_, S_, S_, D_,
                                     SS_, (size_t)H_ * SS_,
                                     (size_t)64 * S_, (size_t)H_ * 64 * S_,
                                     64, (size_t)S_ * D_, 1.0f);

    // launch 7: out = x @ Wo^T  (128 CTAs = single wave)
    dim3 gout(D_ / 128, M_ / 256, 1);
    gemm_f32<<<gout, 256, SMEM_BIG>>>(xh, xl, wh + 3 * DD_, wl + 3 * DD_,
                                      out, nullptr, nullptr,
                                      D_, D_, D_, D_, 0, 0, 0, 0, 0, 0, 1.0f);
}

// round 16
// speedup vs baseline: 1.0495x; 1.0495x over previous
#include <cuda_runtime.h>
#include <cuda_bf16.h>
#include <cstdint>

// Problem constants (fixed shapes)
constexpr int B_  = 2;
constexpr int S_  = 2048;
constexpr int D_  = 1024;
constexpr int H_  = 16;
constexpr int M_  = B_ * S_;            // 4096
constexpr size_t SS_ = (size_t)S_ * S_; // 4M
constexpr size_t MD_ = (size_t)M_ * D_;
constexpr size_t DD_ = (size_t)D_ * D_;

// ---------------------------------------------------------------------------
// Device-global scratch (pooled for batched GEMM addressing)
// ---------------------------------------------------------------------------
__device__ float g_att[(size_t)B_ * H_ * SS_];            // 512 MB fp32 scores

__device__ __nv_bfloat16 g_att_hi[(size_t)B_ * H_ * SS_]; // 256 MB
__device__ __nv_bfloat16 g_att_lo[(size_t)B_ * H_ * SS_];

__device__ __nv_bfloat16 g_in_hi [3 * MD_], g_in_lo [3 * MD_];  // qi,ki,vi
__device__ __nv_bfloat16 g_w_hi  [4 * DD_], g_w_lo  [4 * DD_];  // Wq,Wk,Wv,Wo
__device__ __nv_bfloat16 g_qkv_hi[3 * MD_], g_qkv_lo[3 * MD_];  // q,k,v
__device__ __nv_bfloat16 g_x_hi  [MD_],     g_x_lo  [MD_];
__device__ __nv_bfloat16 g_vt_hi[(size_t)B_ * H_ * 64 * S_];    // [bh][64][2048]
__device__ __nv_bfloat16 g_vt_lo[(size_t)B_ * H_ * 64 * S_];

// ---------------------------------------------------------------------------
// PTX helpers (compute_103-baseline safe: mma.sync / ldmatrix / cp.async)
// ---------------------------------------------------------------------------
__device__ __forceinline__ uint32_t smem_u32(const void* p) {
    uint32_t a;
    asm("{ .reg .u64 t; cvta.to.shared.u64 t, %1; cvt.u32.u64 %0, t; }"
        : "=r"(a) : "l"(p));
    return a;
}
__device__ __forceinline__ void cp16(uint32_t dst, const void* src) {
    asm volatile("cp.async.cg.shared.global [%0], [%1], 16;"
                 :: "r"(dst), "l"(src));
}
#define CP_COMMIT() asm volatile("cp.async.commit_group;" ::: "memory")
#define CP_WAIT(n)  asm volatile("cp.async.wait_group %0;" :: "n"(n) : "memory")

#define LDSM_X4(r, addr)                                                       \
    asm volatile("ldmatrix.sync.aligned.m8n8.x4.shared.b16 {%0,%1,%2,%3},[%4];"\
                 : "=r"((r)[0]), "=r"((r)[1]), "=r"((r)[2]), "=r"((r)[3])      \
                 : "r"(addr))
#define LDSM_X2(r, addr)                                                       \
    asm volatile("ldmatrix.sync.aligned.m8n8.x2.shared.b16 {%0,%1},[%2];"      \
                 : "=r"((r)[0]), "=r"((r)[1]) : "r"(addr))
#define MMA16816(c, a, b)                                                      \
    asm volatile("mma.sync.aligned.m16n8k16.row.col.f32.bf16.bf16.f32 "        \
                 "{%0,%1,%2,%3},{%4,%5,%6,%7},{%8,%9},{%0,%1,%2,%3};"          \
                 : "+f"((c)[0]), "+f"((c)[1]), "+f"((c)[2]), "+f"((c)[3])      \
                 : "r"((a)[0]), "r"((a)[1]), "r"((a)[2]), "r"((a)[3]),         \
                   "r"((b)[0]), "r"((b)[1]))

__device__ __forceinline__ __nv_bfloat162 split_pair(float a, float b,
                                                     __nv_bfloat162& lo) {
    __nv_bfloat16 ha = __float2bfloat16(a);
    __nv_bfloat16 hb = __float2bfloat16(b);
    lo = __nv_bfloat162(__float2bfloat16(a - __bfloat162float(ha)),
                        __float2bfloat16(b - __bfloat162float(hb)));
    return __nv_bfloat162(ha, hb);
}

__device__ __forceinline__ void split_store4(const float4* x,
                                             __nv_bfloat162* hi,
                                             __nv_bfloat162* lo, int i) {
    float4 v = x[i];
    __nv_bfloat162 l0, l1;
    __nv_bfloat162 h0 = split_pair(v.x, v.y, l0);
    __nv_bfloat162 h1 = split_pair(v.z, v.w, l1);
    hi[2 * i] = h0; hi[2 * i + 1] = h1;
    lo[2 * i] = l0; lo[2 * i + 1] = l1;
}

// ---------------------------------------------------------------------------
// Fused splits into pooled buffers
// ---------------------------------------------------------------------------
__global__ __launch_bounds__(256) void split3_kernel(
    const float4* __restrict__ s0, const float4* __restrict__ s1,
    const float4* __restrict__ s2,
    __nv_bfloat162* __restrict__ hi, __nv_bfloat162* __restrict__ lo, int n4)
{
    int i = blockIdx.x * 256 + threadIdx.x;
    const float4* s = blockIdx.y == 0 ? s0 : blockIdx.y == 1 ? s1 : s2;
    split_store4(s, hi + (size_t)blockIdx.y * n4 * 2,
                 lo + (size_t)blockIdx.y * n4 * 2, i);
}

__global__ __launch_bounds__(256) void split4_kernel(
    const float4* __restrict__ s0, const float4* __restrict__ s1,
    const float4* __restrict__ s2, const float4* __restrict__ s3,
    __nv_bfloat162* __restrict__ hi, __nv_bfloat162* __restrict__ lo, int n4)
{
    int i = blockIdx.x * 256 + threadIdx.x;
    const float4* s = blockIdx.y == 0 ? s0 : blockIdx.y == 1 ? s1
                    : blockIdx.y == 2 ? s2 : s3;
    split_store4(s, hi + (size_t)blockIdx.y * n4 * 2,
                 lo + (size_t)blockIdx.y * n4 * 2, i);
}

// ---------------------------------------------------------------------------
// V hi/lo [b, k(2048), d(1024)] bf16 -> Vt hi/lo [bh, d(64), k(2048)] bf16
// ---------------------------------------------------------------------------
__global__ __launch_bounds__(256) void transpose_v_bf16(
    const __nv_bfloat16* __restrict__ Vh, const __nv_bfloat16* __restrict__ Vl,
    __nv_bfloat16* __restrict__ hi, __nv_bfloat16* __restrict__ lo)
{
    __shared__ __nv_bfloat16 th[32][34], tl[32][34];
    const int b  = blockIdx.z;
    const int k0 = blockIdx.y * 32;
    const int d0 = blockIdx.x * 32;
    const int tx = threadIdx.x & 31, ty = threadIdx.x >> 5;
#pragma unroll
    for (int i = 0; i < 4; i++) {
        int k = k0 + ty + i * 8;
        size_t src = ((size_t)b * S_ + k) * D_ + d0 + tx;
        th[ty + i * 8][tx] = Vh[src];
        tl[ty + i * 8][tx] = Vl[src];
    }
    __syncthreads();
#pragma unroll
    for (int i = 0; i < 4; i++) {
        int d = d0 + ty + i * 8;
        int h = d >> 6, dh = d & 63;
        size_t o = ((size_t)(b * H_ + h) * 64 + dh) * S_ + k0 + tx;
        hi[o] = th[tx][ty + i * 8];
        lo[o] = tl[tx][ty + i * 8];
    }
}

// ---------------------------------------------------------------------------
// Generic NT bf16x3 GEMM, 256 threads, 2-stage cp.async.
// Templated macro-tile (BM, BN) AND K-chunk depth (BK).
// C[M,N](+scale) = (Ahi+Alo)[M,K] @ (Bhi+Blo)[N,K]^T
// OUT16=0: fp32 C.  OUT16=1: bf16 hi/lo (Chi, Clo).
// Per-z offsets: off = (z&15)*zs1 + (z>>4)*zs2.
// ---------------------------------------------------------------------------
template<int BM, int BN, int BK, int WGM, int WGN, int OUT16>
__global__ __launch_bounds__(256, 1) void gemm_bf16x3_mma(
    const __nv_bfloat16* __restrict__ Ahi, const __nv_bfloat16* __restrict__ Alo,
    const __nv_bfloat16* __restrict__ Bhi, const __nv_bfloat16* __restrict__ Blo,
    float* __restrict__ C, __nv_bfloat16* __restrict__ Chi,
    __nv_bfloat16* __restrict__ Clo, int K, int lda, int ldb, int ldc,
    size_t zsA1, size_t zsA2, size_t zsB1, size_t zsB2,
    size_t zsC1, size_t zsC2, float scale)
{
    constexpr int NTHR = 256;
    constexpr int WTM = BM / WGM;
    constexpr int WTN = BN / WGN;
    constexpr int MT  = WTM / 16;
    constexpr int NT  = WTN / 8;
    constexpr int KS  = BK / 16;            // ks-steps per chunk
    constexpr int RC  = BK / 8;             // 16B chunks per row
    constexpr int LDSR = BK + 8;
    constexpr int A_BYTES = BM * LDSR * 2;
    constexpr int B_BYTES = BN * LDSR * 2;
    constexpr int STAGE   = 2 * A_BYTES + 2 * B_BYTES;
    constexpr int CHUNKS  = (2 * BM + 2 * BN) * RC;
    static_assert(CHUNKS % NTHR == 0, "loader balance");

    extern __shared__ char smem_raw[];
    const uint32_t sbase = smem_u32(smem_raw);

    const int tid  = threadIdx.x;
    const int wid  = tid >> 5, lane = tid & 31;
    const int wm   = wid / WGN, wn = wid % WGN;
    const int bm   = blockIdx.y * BM;
    const int bn   = blockIdx.x * BN;
    const int z    = blockIdx.z;

    const size_t offA = (size_t)(z & 15) * zsA1 + (size_t)(z >> 4) * zsA2;
    const size_t offB = (size_t)(z & 15) * zsB1 + (size_t)(z >> 4) * zsB2;
    const size_t offC = (size_t)(z & 15) * zsC1 + (size_t)(z >> 4) * zsC2;
    const __nv_bfloat16* pAh = Ahi + offA;
    const __nv_bfloat16* pAl = Alo + offA;
    const __nv_bfloat16* pBh = Bhi + offB;
    const __nv_bfloat16* pBl = Blo + offB;

    float acc[MT][NT][4];
#pragma unroll
    for (int i = 0; i < MT; i++)
#pragma unroll
        for (int j = 0; j < NT; j++)
#pragma unroll
            for (int q = 0; q < 4; q++) acc[i][j][q] = 0.0f;

    const int NC = K / BK;

    auto issue = [&](int c) {
        const uint32_t sb = sbase + (uint32_t)(c & 1) * STAGE;
        const int k0 = c * BK;
#pragma unroll
        for (int it = 0; it < CHUNKS / NTHR; it++) {
            int idx = tid + it * NTHR;
            int r4 = idx / RC, kc = idx % RC;
            const __nv_bfloat16* src;
            uint32_t dst;
            if (r4 < BM) {
                src = pAh + (size_t)(bm + r4) * lda + k0 + kc * 8;
                dst = sb + (uint32_t)(r4 * (LDSR * 2) + kc * 16);
            } else if (r4 < 2 * BM) {
                int r = r4 - BM;
                src = pAl + (size_t)(bm + r) * lda + k0 + kc * 8;
                dst = sb + A_BYTES + (uint32_t)(r * (LDSR * 2) + kc * 16);
            } else if (r4 < 2 * BM + BN) {
                int r = r4 - 2 * BM;
                src = pBh + (size_t)(bn + r) * ldb + k0 + kc * 8;
                dst = sb + 2 * A_BYTES + (uint32_t)(r * (LDSR * 2) + kc * 16);
            } else {
                int r = r4 - 2 * BM - BN;
                src = pBl + (size_t)(bn + r) * ldb + k0 + kc * 8;
                dst = sb + 2 * A_BYTES + B_BYTES + (uint32_t)(r * (LDSR * 2) + kc * 16);
            }
            cp16(dst, src);
        }
        CP_COMMIT();
    };

    issue(0);

    for (int c = 0; c < NC; c++) {
        if (c + 1 < NC) { issue(c + 1); CP_WAIT(1); }
        else            { CP_WAIT(0); }
        __syncthreads();

        const uint32_t sA  = sbase + (uint32_t)(c & 1) * STAGE;
        const uint32_t sB  = sA + 2 * A_BYTES;

        const int arow = lane & 15;
        const int acb  = (lane >> 4) * 8;
        const int brow = lane & 7;
        const int bcb  = ((lane >> 3) & 1) * 8;

#pragma unroll
        for (int ks = 0; ks < KS; ks++) {
            uint32_t ahi[MT][4], alo[MT][4], bhi[NT][2], blo[NT][2];
#pragma unroll
            for (int mt = 0; mt < MT; mt++) {
                uint32_t off = (uint32_t)(((wm * WTM + mt * 16 + arow) * LDSR
                                           + ks * 16 + acb) * 2);
                LDSM_X4(ahi[mt], sA + off);
                LDSM_X4(alo[mt], sA + A_BYTES + off);
            }
#pragma unroll
            for (int nt = 0; nt < NT; nt++) {
                uint32_t off = (uint32_t)(((wn * WTN + nt * 8 + brow) * LDSR
                                           + ks * 16 + bcb) * 2);
                LDSM_X2(bhi[nt], sB + off);
                LDSM_X2(blo[nt], sB + B_BYTES + off);
            }
#pragma unroll
            for (int mt = 0; mt < MT; mt++)
#pragma unroll
                for (int nt = 0; nt < NT; nt++) {
                    MMA16816(acc[mt][nt], ahi[mt], bhi[nt]);
                    MMA16816(acc[mt][nt], ahi[mt], blo[nt]);
                    MMA16816(acc[mt][nt], alo[mt], bhi[nt]);
                }
        }
        __syncthreads();
    }

    const int erow = lane >> 2;
    const int ecol = 2 * (lane & 3);
#pragma unroll
    for (int mt = 0; mt < MT; mt++) {
        const int row = bm + wm * WTM + mt * 16 + erow;
#pragma unroll
        for (int nt = 0; nt < NT; nt++) {
            const int col = bn + wn * WTN + nt * 8 + ecol;
            if constexpr (OUT16) {
                __nv_bfloat162 l0, l1;
                __nv_bfloat162 h0 = split_pair(acc[mt][nt][0] * scale,
                                               acc[mt][nt][1] * scale, l0);
                __nv_bfloat162 h1 = split_pair(acc[mt][nt][2] * scale,
                                               acc[mt][nt][3] * scale, l1);
                size_t o0 = offC + (size_t)row * ldc + col;
                size_t o1 = offC + (size_t)(row + 8) * ldc + col;
                *(__nv_bfloat162*)(Chi + o0) = h0;
                *(__nv_bfloat162*)(Clo + o0) = l0;
                *(__nv_bfloat162*)(Chi + o1) = h1;
                *(__nv_bfloat162*)(Clo + o1) = l1;
            } else {
                float* pC = C + offC;
                *(float2*)(pC + (size_t)row * ldc + col) =
                    make_float2(acc[mt][nt][0] * scale, acc[mt][nt][1] * scale);
                *(float2*)(pC + (size_t)(row + 8) * ldc + col) =
                    make_float2(acc[mt][nt][2] * scale, acc[mt][nt][3] * scale);
            }
        }
    }
}

// ---------------------------------------------------------------------------
// softmax over the HEAD axis, float2-vectorized; emits attn as bf16 hi/lo.
// ---------------------------------------------------------------------------
__global__ __launch_bounds__(256) void softmax_h_split_v2(
    const float* __restrict__ att, __nv_bfloat16* __restrict__ hi,
    __nv_bfloat16* __restrict__ lo)
{
    const size_t SS2 = SS_ / 2;
    size_t idx = (size_t)blockIdx.x * 256 + threadIdx.x;
    size_t b   = idx >> 21;
    size_t rem = idx & (SS2 - 1);
    size_t base = b * (size_t)H_ * SS_ + rem * 2;

    float2 v[H_];
    float mx = -1e30f, my = -1e30f;
#pragma unroll
    for (int h = 0; h < H_; h++) {
        v[h] = *(const float2*)(att + base + (size_t)h * SS_);
        mx = fmaxf(mx, v[h].x);
        my = fmaxf(my, v[h].y);
    }
    float sx = 0.0f, sy = 0.0f;
#pragma unroll
    for (int h = 0; h < H_; h++) {
        v[h].x = __expf(v[h].x - mx);
        v[h].y = __expf(v[h].y - my);
        sx += v[h].x;
        sy += v[h].y;
    }
    float ix = 1.0f / sx, iy = 1.0f / sy;
#pragma unroll
    for (int h = 0; h < H_; h++) {
        float px = v[h].x * ix, py = v[h].y * iy;
        __nv_bfloat162 l;
        __nv_bfloat162 hv = split_pair(px, py, l);
        size_t o = base + (size_t)h * SS_;
        *(__nv_bfloat162*)(hi + o) = hv;
        *(__nv_bfloat162*)(lo + o) = l;
    }
}

// ---------------------------------------------------------------------------
extern "C" void kernel_launch(void* const* d_in, const int* in_sizes, int n_in,
                              void* d_out, int out_size)
{
    (void)in_sizes; (void)n_in; (void)out_size;
    const float* qi = (const float*)d_in[0];
    const float* ki = (const float*)d_in[1];
    const float* vi = (const float*)d_in[2];
    // d_in[3] = mask: reference discards masked_fill -> unused
    const float* Wq = (const float*)d_in[4];
    const float* Wk = (const float*)d_in[5];
    const float* Wv = (const float*)d_in[6];
    const float* Wo = (const float*)d_in[7];
    float* out = (float*)d_out;

    float* gatt;
    cudaGetSymbolAddress((void**)&gatt, g_att);

    __nv_bfloat16 *inh, *inl, *wh, *wl, *qkvh, *qkvl, *xh, *xl, *vth, *vtl, *ath, *atl;
    cudaGetSymbolAddress((void**)&inh,  g_in_hi);  cudaGetSymbolAddress((void**)&inl,  g_in_lo);
    cudaGetSymbolAddress((void**)&wh,   g_w_hi);   cudaGetSymbolAddress((void**)&wl,   g_w_lo);
    cudaGetSymbolAddress((void**)&qkvh, g_qkv_hi); cudaGetSymbolAddress((void**)&qkvl, g_qkv_lo);
    cudaGetSymbolAddress((void**)&xh,   g_x_hi);   cudaGetSymbolAddress((void**)&xl,   g_x_lo);
    cudaGetSymbolAddress((void**)&vth,  g_vt_hi);  cudaGetSymbolAddress((void**)&vtl,  g_vt_lo);
    cudaGetSymbolAddress((void**)&ath,  g_att_hi); cudaGetSymbolAddress((void**)&atl,  g_att_lo);

    // R10-proven tiles: 256x128/BK32 big; attn@V: 128x64/BK64 (R10 lever via BK).
    auto* gemm_f32 = gemm_bf16x3_mma<256, 128, 32, 4, 2, 0>;
    auto* gemm_b16 = gemm_bf16x3_mma<256, 128, 32, 4, 2, 1>;
    auto* gemm_nar = gemm_bf16x3_mma<128, 64, 64, 4, 2, 1>;
    constexpr int SMEM_BIG = 2 * (2 * 256 * 40 * 2 + 2 * 128 * 40 * 2); // 122880
    constexpr int SMEM_NAR = 2 * (2 * 128 * 72 * 2 + 2 * 64 * 72 * 2);  // 110592
    cudaFuncSetAttribute(gemm_f32, cudaFuncAttributeMaxDynamicSharedMemorySize, SMEM_BIG);
    cudaFuncSetAttribute(gemm_b16, cudaFuncAttributeMaxDynamicSharedMemorySize, SMEM_BIG);
    cudaFuncSetAttribute(gemm_nar, cudaFuncAttributeMaxDynamicSharedMemorySize, SMEM_NAR);

    const int nInp4 = (int)(MD_ / 4);   // 1,048,576
    const int nW4   = (int)(DD_ / 4);   // 262,144

    // launch 0: split inputs (qi, ki, vi) -> pooled g_in
    dim3 gs3(nInp4 / 256, 3);
    split3_kernel<<<gs3, 256>>>((const float4*)qi, (const float4*)ki, (const float4*)vi,
                                (__nv_bfloat162*)inh, (__nv_bfloat162*)inl, nInp4);

    // launch 1: split weights -> pooled g_w
    dim3 gs4(nW4 / 256, 4);
    split4_kernel<<<gs4, 256>>>((const float4*)Wq, (const float4*)Wk,
                                (const float4*)Wv, (const float4*)Wo,
                                (__nv_bfloat162*)wh, (__nv_bfloat162*)wl, nW4);

    // launch 2: batched Q/K/V projections (z selects), emit bf16 hi/lo
    dim3 gproj(D_ / 128, M_ / 256, 3);   // (8, 16, 3) = 384 CTAs
    gemm_b16<<<gproj, 256, SMEM_BIG>>>(inh, inl, wh, wl, nullptr, qkvh, qkvl,
                                       D_, D_, D_, D_,
                                       MD_, 0, DD_, 0, MD_, 0, 1.0f);

    // launch 3 (ncu capture slot): scores[bh] = (Q_h @ K_h^T) / 8  (fp32)
    dim3 gsc(S_ / 128, S_ / 256, B_ * H_);   // (16, 8, 32) = 4096 CTAs
    gemm_f32<<<gsc, 256, SMEM_BIG>>>(qkvh, qkvl, qkvh + MD_, qkvl + MD_,
                                     gatt, nullptr, nullptr,
                                     64, D_, D_, S_,
                                     64, (size_t)S_ * D_,
                                     64, (size_t)S_ * D_,
                                     SS_, (size_t)H_ * SS_, 0.125f);

    // launch 4: transpose v hi/lo -> [bh][64][2048]
    dim3 gtr(D_ / 32, S_ / 32, B_);
    transpose_v_bf16<<<gtr, 256>>>(qkvh + 2 * MD_, qkvl + 2 * MD_, vth, vtl);

    // launch 5: softmax over heads (float2-vectorized) -> attn hi/lo bf16
    int smx_blocks = (int)(((size_t)B_ * SS_ / 2) / 256);   // 16384
    softmax_h_split_v2<<<smx_blocks, 256>>>(gatt, ath, atl);

    // launch 6: x[bh] = attn[bh] @ Vt[bh]^T  (N=64, BK=64), emits bf16 hi/lo
    dim3 gav(1, S_ / 128, B_ * H_);      // (1, 16, 32) = 512 CTAs
    gemm_nar<<<gav, 256, SMEM_NAR>>>(ath, atl, vth, vtl, nullptr, xh, xl,
                                     S_, S_, S_, D_,
                                     SS_, (size_t)H_ * SS_,
                                     (size_t)64 * S_, (size_t)H_ * 64 * S_,
                                     64, (size_t)S_ * D_, 1.0f);

    // launch 7: out = x @ Wo^T  (128 CTAs = single wave)
    dim3 gout(D_ / 128, M_ / 256, 1);
    gemm_f32<<<gout, 256, SMEM_BIG>>>(xh, xl, wh + 3 * DD_, wl + 3 * DD_,
                                      out, nullptr, nullptr,
                                      D_, D_, D_, D_, 0, 0, 0, 0, 0, 0, 1.0f);
}

// round 17
// speedup vs baseline: 1.0607x; 1.0107x over previous
#include <cuda_runtime.h>
#include <cuda_bf16.h>
#include <cstdint>

// Problem constants (fixed shapes)
constexpr int B_  = 2;
constexpr int S_  = 2048;
constexpr int D_  = 1024;
constexpr int H_  = 16;
constexpr int M_  = B_ * S_;            // 4096
constexpr size_t SS_ = (size_t)S_ * S_; // 4M
constexpr size_t MD_ = (size_t)M_ * D_;
constexpr size_t DD_ = (size_t)D_ * D_;

// ---------------------------------------------------------------------------
// Device-global scratch (pooled for batched GEMM addressing)
// ---------------------------------------------------------------------------
__device__ float g_att[(size_t)B_ * H_ * SS_];            // 512 MB fp32 scores

__device__ __nv_bfloat16 g_att_hi[(size_t)B_ * H_ * SS_]; // 256 MB
__device__ __nv_bfloat16 g_att_lo[(size_t)B_ * H_ * SS_];

__device__ __nv_bfloat16 g_in_hi [3 * MD_], g_in_lo [3 * MD_];  // qi,ki,vi
__device__ __nv_bfloat16 g_w_hi  [4 * DD_], g_w_lo  [4 * DD_];  // Wq,Wk,Wv,Wo
__device__ __nv_bfloat16 g_qkv_hi[3 * MD_], g_qkv_lo[3 * MD_];  // q,k,v
__device__ __nv_bfloat16 g_x_hi  [MD_],     g_x_lo  [MD_];
__device__ __nv_bfloat16 g_vt_hi[(size_t)B_ * H_ * 64 * S_];    // [bh][64][2048]
__device__ __nv_bfloat16 g_vt_lo[(size_t)B_ * H_ * 64 * S_];

// ---------------------------------------------------------------------------
// PTX helpers (compute_103-baseline safe: mma.sync / ldmatrix / cp.async)
// ---------------------------------------------------------------------------
__device__ __forceinline__ uint32_t smem_u32(const void* p) {
    uint32_t a;
    asm("{ .reg .u64 t; cvta.to.shared.u64 t, %1; cvt.u32.u64 %0, t; }"
        : "=r"(a) : "l"(p));
    return a;
}
__device__ __forceinline__ void cp16(uint32_t dst, const void* src) {
    asm volatile("cp.async.cg.shared.global [%0], [%1], 16;"
                 :: "r"(dst), "l"(src));
}
#define CP_COMMIT() asm volatile("cp.async.commit_group;" ::: "memory")
#define CP_WAIT(n)  asm volatile("cp.async.wait_group %0;" :: "n"(n) : "memory")

#define LDSM_X4(r, addr)                                                       \
    asm volatile("ldmatrix.sync.aligned.m8n8.x4.shared.b16 {%0,%1,%2,%3},[%4];"\
                 : "=r"((r)[0]), "=r"((r)[1]), "=r"((r)[2]), "=r"((r)[3])      \
                 : "r"(addr))
#define LDSM_X2(r, addr)                                                       \
    asm volatile("ldmatrix.sync.aligned.m8n8.x2.shared.b16 {%0,%1},[%2];"      \
                 : "=r"((r)[0]), "=r"((r)[1]) : "r"(addr))
#define MMA16816(c, a, b)                                                      \
    asm volatile("mma.sync.aligned.m16n8k16.row.col.f32.bf16.bf16.f32 "        \
                 "{%0,%1,%2,%3},{%4,%5,%6,%7},{%8,%9},{%0,%1,%2,%3};"          \
                 : "+f"((c)[0]), "+f"((c)[1]), "+f"((c)[2]), "+f"((c)[3])      \
                 : "r"((a)[0]), "r"((a)[1]), "r"((a)[2]), "r"((a)[3]),         \
                   "r"((b)[0]), "r"((b)[1]))

__device__ __forceinline__ __nv_bfloat162 split_pair(float a, float b,
                                                     __nv_bfloat162& lo) {
    __nv_bfloat16 ha = __float2bfloat16(a);
    __nv_bfloat16 hb = __float2bfloat16(b);
    lo = __nv_bfloat162(__float2bfloat16(a - __bfloat162float(ha)),
                        __float2bfloat16(b - __bfloat162float(hb)));
    return __nv_bfloat162(ha, hb);
}

__device__ __forceinline__ void split_store4(const float4* x,
                                             __nv_bfloat162* hi,
                                             __nv_bfloat162* lo, int i) {
    float4 v = x[i];
    __nv_bfloat162 l0, l1;
    __nv_bfloat162 h0 = split_pair(v.x, v.y, l0);
    __nv_bfloat162 h1 = split_pair(v.z, v.w, l1);
    hi[2 * i] = h0; hi[2 * i + 1] = h1;
    lo[2 * i] = l0; lo[2 * i + 1] = l1;
}

// ---------------------------------------------------------------------------
// Fused splits into pooled buffers
// ---------------------------------------------------------------------------
__global__ __launch_bounds__(256) void split3_kernel(
    const float4* __restrict__ s0, const float4* __restrict__ s1,
    const float4* __restrict__ s2,
    __nv_bfloat162* __restrict__ hi, __nv_bfloat162* __restrict__ lo, int n4)
{
    int i = blockIdx.x * 256 + threadIdx.x;
    const float4* s = blockIdx.y == 0 ? s0 : blockIdx.y == 1 ? s1 : s2;
    split_store4(s, hi + (size_t)blockIdx.y * n4 * 2,
                 lo + (size_t)blockIdx.y * n4 * 2, i);
}

__global__ __launch_bounds__(256) void split4_kernel(
    const float4* __restrict__ s0, const float4* __restrict__ s1,
    const float4* __restrict__ s2, const float4* __restrict__ s3,
    __nv_bfloat162* __restrict__ hi, __nv_bfloat162* __restrict__ lo, int n4)
{
    int i = blockIdx.x * 256 + threadIdx.x;
    const float4* s = blockIdx.y == 0 ? s0 : blockIdx.y == 1 ? s1
                    : blockIdx.y == 2 ? s2 : s3;
    split_store4(s, hi + (size_t)blockIdx.y * n4 * 2,
                 lo + (size_t)blockIdx.y * n4 * 2, i);
}

// ---------------------------------------------------------------------------
// V hi/lo [b, k(2048), d(1024)] bf16 -> Vt hi/lo [bh, d(64), k(2048)] bf16
// ---------------------------------------------------------------------------
__global__ __launch_bounds__(256) void transpose_v_bf16(
    const __nv_bfloat16* __restrict__ Vh, const __nv_bfloat16* __restrict__ Vl,
    __nv_bfloat16* __restrict__ hi, __nv_bfloat16* __restrict__ lo)
{
    __shared__ __nv_bfloat16 th[32][34], tl[32][34];
    const int b  = blockIdx.z;
    const int k0 = blockIdx.y * 32;
    const int d0 = blockIdx.x * 32;
    const int tx = threadIdx.x & 31, ty = threadIdx.x >> 5;
#pragma unroll
    for (int i = 0; i < 4; i++) {
        int k = k0 + ty + i * 8;
        size_t src = ((size_t)b * S_ + k) * D_ + d0 + tx;
        th[ty + i * 8][tx] = Vh[src];
        tl[ty + i * 8][tx] = Vl[src];
    }
    __syncthreads();
#pragma unroll
    for (int i = 0; i < 4; i++) {
        int d = d0 + ty + i * 8;
        int h = d >> 6, dh = d & 63;
        size_t o = ((size_t)(b * H_ + h) * 64 + dh) * S_ + k0 + tx;
        hi[o] = th[tx][ty + i * 8];
        lo[o] = tl[tx][ty + i * 8];
    }
}

// ---------------------------------------------------------------------------
// Generic NT bf16x3 GEMM, 256 threads, 2-stage cp.async.
// Templated macro-tile (BM, BN) AND K-chunk depth (BK).
// C[M,N](+scale) = (Ahi+Alo)[M,K] @ (Bhi+Blo)[N,K]^T
// OUT16=0: fp32 C.  OUT16=1: bf16 hi/lo (Chi, Clo).
// Per-z offsets: off = (z&15)*zs1 + (z>>4)*zs2.
// ---------------------------------------------------------------------------
template<int BM, int BN, int BK, int WGM, int WGN, int OUT16>
__global__ __launch_bounds__(256, 1) void gemm_bf16x3_mma(
    const __nv_bfloat16* __restrict__ Ahi, const __nv_bfloat16* __restrict__ Alo,
    const __nv_bfloat16* __restrict__ Bhi, const __nv_bfloat16* __restrict__ Blo,
    float* __restrict__ C, __nv_bfloat16* __restrict__ Chi,
    __nv_bfloat16* __restrict__ Clo, int K, int lda, int ldb, int ldc,
    size_t zsA1, size_t zsA2, size_t zsB1, size_t zsB2,
    size_t zsC1, size_t zsC2, float scale)
{
    constexpr int NTHR = 256;
    constexpr int WTM = BM / WGM;
    constexpr int WTN = BN / WGN;
    constexpr int MT  = WTM / 16;
    constexpr int NT  = WTN / 8;
    constexpr int KS  = BK / 16;            // ks-steps per chunk
    constexpr int RC  = BK / 8;             // 16B chunks per row
    constexpr int LDSR = BK + 8;
    constexpr int A_BYTES = BM * LDSR * 2;
    constexpr int B_BYTES = BN * LDSR * 2;
    constexpr int STAGE   = 2 * A_BYTES + 2 * B_BYTES;
    constexpr int CHUNKS  = (2 * BM + 2 * BN) * RC;
    static_assert(CHUNKS % NTHR == 0, "loader balance");

    extern __shared__ char smem_raw[];
    const uint32_t sbase = smem_u32(smem_raw);

    const int tid  = threadIdx.x;
    const int wid  = tid >> 5, lane = tid & 31;
    const int wm   = wid / WGN, wn = wid % WGN;
    const int bm   = blockIdx.y * BM;
    const int bn   = blockIdx.x * BN;
    const int z    = blockIdx.z;

    const size_t offA = (size_t)(z & 15) * zsA1 + (size_t)(z >> 4) * zsA2;
    const size_t offB = (size_t)(z & 15) * zsB1 + (size_t)(z >> 4) * zsB2;
    const size_t offC = (size_t)(z & 15) * zsC1 + (size_t)(z >> 4) * zsC2;
    const __nv_bfloat16* pAh = Ahi + offA;
    const __nv_bfloat16* pAl = Alo + offA;
    const __nv_bfloat16* pBh = Bhi + offB;
    const __nv_bfloat16* pBl = Blo + offB;

    float acc[MT][NT][4];
#pragma unroll
    for (int i = 0; i < MT; i++)
#pragma unroll
        for (int j = 0; j < NT; j++)
#pragma unroll
            for (int q = 0; q < 4; q++) acc[i][j][q] = 0.0f;

    const int NC = K / BK;

    auto issue = [&](int c) {
        const uint32_t sb = sbase + (uint32_t)(c & 1) * STAGE;
        const int k0 = c * BK;
#pragma unroll
        for (int it = 0; it < CHUNKS / NTHR; it++) {
            int idx = tid + it * NTHR;
            int r4 = idx / RC, kc = idx % RC;
            const __nv_bfloat16* src;
            uint32_t dst;
            if (r4 < BM) {
                src = pAh + (size_t)(bm + r4) * lda + k0 + kc * 8;
                dst = sb + (uint32_t)(r4 * (LDSR * 2) + kc * 16);
            } else if (r4 < 2 * BM) {
                int r = r4 - BM;
                src = pAl + (size_t)(bm + r) * lda + k0 + kc * 8;
                dst = sb + A_BYTES + (uint32_t)(r * (LDSR * 2) + kc * 16);
            } else if (r4 < 2 * BM + BN) {
                int r = r4 - 2 * BM;
                src = pBh + (size_t)(bn + r) * ldb + k0 + kc * 8;
                dst = sb + 2 * A_BYTES + (uint32_t)(r * (LDSR * 2) + kc * 16);
            } else {
                int r = r4 - 2 * BM - BN;
                src = pBl + (size_t)(bn + r) * ldb + k0 + kc * 8;
                dst = sb + 2 * A_BYTES + B_BYTES + (uint32_t)(r * (LDSR * 2) + kc * 16);
            }
            cp16(dst, src);
        }
        CP_COMMIT();
    };

    issue(0);

    for (int c = 0; c < NC; c++) {
        if (c + 1 < NC) { issue(c + 1); CP_WAIT(1); }
        else            { CP_WAIT(0); }
        __syncthreads();

        const uint32_t sA  = sbase + (uint32_t)(c & 1) * STAGE;
        const uint32_t sB  = sA + 2 * A_BYTES;

        const int arow = lane & 15;
        const int acb  = (lane >> 4) * 8;
        const int brow = lane & 7;
        const int bcb  = ((lane >> 3) & 1) * 8;

#pragma unroll
        for (int ks = 0; ks < KS; ks++) {
            uint32_t ahi[MT][4], alo[MT][4], bhi[NT][2], blo[NT][2];
#pragma unroll
            for (int mt = 0; mt < MT; mt++) {
                uint32_t off = (uint32_t)(((wm * WTM + mt * 16 + arow) * LDSR
                                           + ks * 16 + acb) * 2);
                LDSM_X4(ahi[mt], sA + off);
                LDSM_X4(alo[mt], sA + A_BYTES + off);
            }
#pragma unroll
            for (int nt = 0; nt < NT; nt++) {
                uint32_t off = (uint32_t)(((wn * WTN + nt * 8 + brow) * LDSR
                                           + ks * 16 + bcb) * 2);
                LDSM_X2(bhi[nt], sB + off);
                LDSM_X2(blo[nt], sB + B_BYTES + off);
            }
#pragma unroll
            for (int mt = 0; mt < MT; mt++)
#pragma unroll
                for (int nt = 0; nt < NT; nt++) {
                    MMA16816(acc[mt][nt], ahi[mt], bhi[nt]);
                    MMA16816(acc[mt][nt], ahi[mt], blo[nt]);
                    MMA16816(acc[mt][nt], alo[mt], bhi[nt]);
                }
        }
        __syncthreads();
    }

    const int erow = lane >> 2;
    const int ecol = 2 * (lane & 3);
#pragma unroll
    for (int mt = 0; mt < MT; mt++) {
        const int row = bm + wm * WTM + mt * 16 + erow;
#pragma unroll
        for (int nt = 0; nt < NT; nt++) {
            const int col = bn + wn * WTN + nt * 8 + ecol;
            if constexpr (OUT16) {
                __nv_bfloat162 l0, l1;
                __nv_bfloat162 h0 = split_pair(acc[mt][nt][0] * scale,
                                               acc[mt][nt][1] * scale, l0);
                __nv_bfloat162 h1 = split_pair(acc[mt][nt][2] * scale,
                                               acc[mt][nt][3] * scale, l1);
                size_t o0 = offC + (size_t)row * ldc + col;
                size_t o1 = offC + (size_t)(row + 8) * ldc + col;
                *(__nv_bfloat162*)(Chi + o0) = h0;
                *(__nv_bfloat162*)(Clo + o0) = l0;
                *(__nv_bfloat162*)(Chi + o1) = h1;
                *(__nv_bfloat162*)(Clo + o1) = l1;
            } else {
                float* pC = C + offC;
                *(float2*)(pC + (size_t)row * ldc + col) =
                    make_float2(acc[mt][nt][0] * scale, acc[mt][nt][1] * scale);
                *(float2*)(pC + (size_t)(row + 8) * ldc + col) =
                    make_float2(acc[mt][nt][2] * scale, acc[mt][nt][3] * scale);
            }
        }
    }
}

// ---------------------------------------------------------------------------
// softmax over the HEAD axis, float2-vectorized; emits attn as bf16 hi/lo.
// ---------------------------------------------------------------------------
__global__ __launch_bounds__(256) void softmax_h_split_v2(
    const float* __restrict__ att, __nv_bfloat16* __restrict__ hi,
    __nv_bfloat16* __restrict__ lo)
{
    const size_t SS2 = SS_ / 2;
    size_t idx = (size_t)blockIdx.x * 256 + threadIdx.x;
    size_t b   = idx >> 21;
    size_t rem = idx & (SS2 - 1);
    size_t base = b * (size_t)H_ * SS_ + rem * 2;

    float2 v[H_];
    float mx = -1e30f, my = -1e30f;
#pragma unroll
    for (int h = 0; h < H_; h++) {
        v[h] = *(const float2*)(att + base + (size_t)h * SS_);
        mx = fmaxf(mx, v[h].x);
        my = fmaxf(my, v[h].y);
    }
    float sx = 0.0f, sy = 0.0f;
#pragma unroll
    for (int h = 0; h < H_; h++) {
        v[h].x = __expf(v[h].x - mx);
        v[h].y = __expf(v[h].y - my);
        sx += v[h].x;
        sy += v[h].y;
    }
    float ix = 1.0f / sx, iy = 1.0f / sy;
#pragma unroll
    for (int h = 0; h < H_; h++) {
        float px = v[h].x * ix, py = v[h].y * iy;
        __nv_bfloat162 l;
        __nv_bfloat162 hv = split_pair(px, py, l);
        size_t o = base + (size_t)h * SS_;
        *(__nv_bfloat162*)(hi + o) = hv;
        *(__nv_bfloat162*)(lo + o) = l;
    }
}

// ---------------------------------------------------------------------------
extern "C" void kernel_launch(void* const* d_in, const int* in_sizes, int n_in,
                              void* d_out, int out_size)
{
    (void)in_sizes; (void)n_in; (void)out_size;
    const float* qi = (const float*)d_in[0];
    const float* ki = (const float*)d_in[1];
    const float* vi = (const float*)d_in[2];
    // d_in[3] = mask: reference discards masked_fill -> unused
    const float* Wq = (const float*)d_in[4];
    const float* Wk = (const float*)d_in[5];
    const float* Wv = (const float*)d_in[6];
    const float* Wo = (const float*)d_in[7];
    float* out = (float*)d_out;

    float* gatt;
    cudaGetSymbolAddress((void**)&gatt, g_att);

    __nv_bfloat16 *inh, *inl, *wh, *wl, *qkvh, *qkvl, *xh, *xl, *vth, *vtl, *ath, *atl;
    cudaGetSymbolAddress((void**)&inh,  g_in_hi);  cudaGetSymbolAddress((void**)&inl,  g_in_lo);
    cudaGetSymbolAddress((void**)&wh,   g_w_hi);   cudaGetSymbolAddress((void**)&wl,   g_w_lo);
    cudaGetSymbolAddress((void**)&qkvh, g_qkv_hi); cudaGetSymbolAddress((void**)&qkvl, g_qkv_lo);
    cudaGetSymbolAddress((void**)&xh,   g_x_hi);   cudaGetSymbolAddress((void**)&xl,   g_x_lo);
    cudaGetSymbolAddress((void**)&vth,  g_vt_hi);  cudaGetSymbolAddress((void**)&vtl,  g_vt_lo);
    cudaGetSymbolAddress((void**)&ath,  g_att_hi); cudaGetSymbolAddress((void**)&atl,  g_att_lo);

    // BK=64 everywhere (R16 lever): projections/out-proj 256x128/BK64,
    // scores 256x128/BK64 (NC=1, zero mid-kernel barriers), attn@V 128x64/BK64.
    auto* gemm_f32 = gemm_bf16x3_mma<256, 128, 64, 4, 2, 0>;
    auto* gemm_b16 = gemm_bf16x3_mma<256, 128, 64, 4, 2, 1>;
    auto* gemm_nar = gemm_bf16x3_mma<128, 64, 64, 4, 2, 1>;
    constexpr int SMEM_BIG = 2 * (2 * 256 * 72 * 2 + 2 * 128 * 72 * 2); // 221184
    constexpr int SMEM_NAR = 2 * (2 * 128 * 72 * 2 + 2 * 64 * 72 * 2);  // 110592
    cudaFuncSetAttribute(gemm_f32, cudaFuncAttributeMaxDynamicSharedMemorySize, SMEM_BIG);
    cudaFuncSetAttribute(gemm_b16, cudaFuncAttributeMaxDynamicSharedMemorySize, SMEM_BIG);
    cudaFuncSetAttribute(gemm_nar, cudaFuncAttributeMaxDynamicSharedMemorySize, SMEM_NAR);

    const int nInp4 = (int)(MD_ / 4);   // 1,048,576
    const int nW4   = (int)(DD_ / 4);   // 262,144

    // launch 0: split inputs (qi, ki, vi) -> pooled g_in
    dim3 gs3(nInp4 / 256, 3);
    split3_kernel<<<gs3, 256>>>((const float4*)qi, (const float4*)ki, (const float4*)vi,
                                (__nv_bfloat162*)inh, (__nv_bfloat162*)inl, nInp4);

    // launch 1: split weights -> pooled g_w
    dim3 gs4(nW4 / 256, 4);
    split4_kernel<<<gs4, 256>>>((const float4*)Wq, (const float4*)Wk,
                                (const float4*)Wv, (const float4*)Wo,
                                (__nv_bfloat162*)wh, (__nv_bfloat162*)wl, nW4);

    // launch 2: batched Q/K/V projections (z selects), emit bf16 hi/lo
    dim3 gproj(D_ / 128, M_ / 256, 3);   // (8, 16, 3) = 384 CTAs
    gemm_b16<<<gproj, 256, SMEM_BIG>>>(inh, inl, wh, wl, nullptr, qkvh, qkvl,
                                       D_, D_, D_, D_,
                                       MD_, 0, DD_, 0, MD_, 0, 1.0f);

    // launch 3 (ncu capture slot): scores[bh] = (Q_h @ K_h^T) / 8  (fp32, NC=1)
    dim3 gsc(S_ / 128, S_ / 256, B_ * H_);   // (16, 8, 32) = 4096 CTAs
    gemm_f32<<<gsc, 256, SMEM_BIG>>>(qkvh, qkvl, qkvh + MD_, qkvl + MD_,
                                     gatt, nullptr, nullptr,
                                     64, D_, D_, S_,
                                     64, (size_t)S_ * D_,
                                     64, (size_t)S_ * D_,
                                     SS_, (size_t)H_ * SS_, 0.125f);

    // launch 4: transpose v hi/lo -> [bh][64][2048]
    dim3 gtr(D_ / 32, S_ / 32, B_);
    transpose_v_bf16<<<gtr, 256>>>(qkvh + 2 * MD_, qkvl + 2 * MD_, vth, vtl);

    // launch 5: softmax over heads (float2-vectorized) -> attn hi/lo bf16
    int smx_blocks = (int)(((size_t)B_ * SS_ / 2) / 256);   // 16384
    softmax_h_split_v2<<<smx_blocks, 256>>>(gatt, ath, atl);

    // launch 6: x[bh] = attn[bh] @ Vt[bh]^T  (N=64, BK=64), emits bf16 hi/lo
    dim3 gav(1, S_ / 128, B_ * H_);      // (1, 16, 32) = 512 CTAs
    gemm_nar<<<gav, 256, SMEM_NAR>>>(ath, atl, vth, vtl, nullptr, xh, xl,
                                     S_, S_, S_, D_,
                                     SS_, (size_t)H_ * SS_,
                                     (size_t)64 * S_, (size_t)H_ * 64 * S_,
                                     64, (size_t)S_ * D_, 1.0f);

    // launch 7: out = x @ Wo^T  (128 CTAs = single wave)
    dim3 gout(D_ / 128, M_ / 256, 1);
    gemm_f32<<<gout, 256, SMEM_BIG>>>(xh, xl, wh + 3 * DD_, wl + 3 * DD_,
                                      out, nullptr, nullptr,
                                      D_, D_, D_, D_, 0, 0, 0, 0, 0, 0, 1.0f);
}